// round 9
// baseline (speedup 1.0000x reference)
#include <cuda_runtime.h>
#include <cuda_bf16.h>
#include <cuda_fp16.h>
#include <stdint.h>

#define NN 100000
#define NE 1250000
#define BKT 64
#define TILE_M 128
#define NTILES ((NN + TILE_M - 1) / TILE_M)   // 782

// ---- static device scratch (no allocations) ----
__device__ int    g_cnt[NN];           // degree counter / scatter cursor
__device__ int    g_src[NN * BKT];     // padded neighbor buckets (25.6 MB)
__device__ __half g_xh[NN * 64];       // fp16 copy of x (12.8 MB)
__device__ __half g_meanh[NN * 64];    // neighbor means, fp16 (12.8 MB)

// ---- k_gemm shared layout (byte offsets; rows 256B, XOR-16B swizzled) ----
#define OFF_AH   0        // A hi: 128 rows x 128 bf16 (x||mean), 32 KB
#define OFF_AL   32768    // A lo, 32 KB
#define OFF_BH   65536    // B hi: 64 rows x 128 bf16 (W'=[Ws|Wn]), 16 KB
#define OFF_BL   81920    // B lo, 16 KB
#define OFF_BIAS 98304    // 64 floats
#define SMEM_USE 98560
#define SMEM_DYN (SMEM_USE + 256)

__device__ __forceinline__ uint32_t s2u(const void* p) {
    uint32_t a;
    asm("{ .reg .u64 t; cvta.to.shared.u64 t, %1; cvt.u32.u64 %0, t; }" : "=r"(a) : "l"(p));
    return a;
}
__device__ __forceinline__ void bsplit(float2 v, uint32_t& h, uint32_t& l) {
    __nv_bfloat162 h2 = __floats2bfloat162_rn(v.x, v.y);
    float hx = __bfloat162float(__low2bfloat16(h2));
    float hy = __bfloat162float(__high2bfloat16(h2));
    __nv_bfloat162 l2 = __floats2bfloat162_rn(v.x - hx, v.y - hy);
    h = *(uint32_t*)&h2;
    l = *(uint32_t*)&l2;
}
__device__ __forceinline__ void ldsm4(uint32_t* r, uint32_t addr) {
    asm volatile("ldmatrix.sync.aligned.m8n8.x4.shared.b16 {%0,%1,%2,%3}, [%4];"
                 : "=r"(r[0]), "=r"(r[1]), "=r"(r[2]), "=r"(r[3]) : "r"(addr));
}
__device__ __forceinline__ void mma16816(float* c, const uint32_t* a, const uint32_t* b) {
    asm volatile(
        "mma.sync.aligned.m16n8k16.row.col.f32.bf16.bf16.f32 "
        "{%0,%1,%2,%3}, {%4,%5,%6,%7}, {%8,%9}, {%0,%1,%2,%3};"
        : "+f"(c[0]), "+f"(c[1]), "+f"(c[2]), "+f"(c[3])
        : "r"(a[0]), "r"(a[1]), "r"(a[2]), "r"(a[3]), "r"(b[0]), "r"(b[1]));
}

// ---------------------------------------------------------------------------
// Convert x -> fp16 copy (streaming, 4 floats/thread).
// ---------------------------------------------------------------------------
__global__ void k_convert(const float* __restrict__ x) {
    int i = blockIdx.x * 256 + threadIdx.x;     // < NN*16
    if (i < NN * 16) {
        float4 v = __ldg((const float4*)x + i);
        __half2 h0 = __floats2half2_rn(v.x, v.y);
        __half2 h1 = __floats2half2_rn(v.z, v.w);
        uint2 o;
        o.x = *(uint32_t*)&h0;
        o.y = *(uint32_t*)&h1;
        ((uint2*)g_xh)[i] = o;
    }
}

// ---------------------------------------------------------------------------
// Scatter edges into padded buckets. 2 edges/thread, 8B index loads.
// ---------------------------------------------------------------------------
__global__ void k_scatter(const int* __restrict__ ei, int E) {
    int t = blockIdx.x * blockDim.x + threadIdx.x;
    int e = t * 2;
    if (e + 1 < E) {
        int2 s = *(const int2*)(ei + e);
        int2 d = *(const int2*)(ei + E + e);
        int p0 = atomicAdd(&g_cnt[d.x], 1);
        if (p0 < BKT) g_src[d.x * BKT + p0] = s.x;
        int p1 = atomicAdd(&g_cnt[d.y], 1);
        if (p1 < BKT) g_src[d.y * BKT + p1] = s.y;
    } else if (e < E) {
        int src = __ldg(ei + e);
        int dst = __ldg(ei + E + e);
        int p = atomicAdd(&g_cnt[dst], 1);
        if (p < BKT) g_src[dst * BKT + p] = src;
    }
}

// ---------------------------------------------------------------------------
// Gather: warp per node; neighbor rows read as fp16 (128B/row), fp32 accum,
// mean stored fp16. Lane covers feature pair (2l, 2l+1).
// ---------------------------------------------------------------------------
__global__ void __launch_bounds__(256)
k_gather() {
    int n = (blockIdx.x * 256 + threadIdx.x) >> 5;
    int lane = threadIdx.x & 31;
    if (n >= NN) return;
    const __half2* xh = (const __half2*)g_xh;

    int degRaw = __ldg(&g_cnt[n]);
    int deg = min(degRaw, BKT);
    const int* bkt = g_src + n * BKT;
    float ax = 0.f, ay = 0.f;
    int e = 0;
    for (; e + 8 <= deg; e += 8) {                  // MLP = 8
        int4 s0 = *(const int4*)(bkt + e);
        int4 s1 = *(const int4*)(bkt + e + 4);
        float2 v0 = __half22float2(__ldg(xh + s0.x * 32 + lane));
        float2 v1 = __half22float2(__ldg(xh + s0.y * 32 + lane));
        float2 v2 = __half22float2(__ldg(xh + s0.z * 32 + lane));
        float2 v3 = __half22float2(__ldg(xh + s0.w * 32 + lane));
        float2 v4 = __half22float2(__ldg(xh + s1.x * 32 + lane));
        float2 v5 = __half22float2(__ldg(xh + s1.y * 32 + lane));
        float2 v6 = __half22float2(__ldg(xh + s1.z * 32 + lane));
        float2 v7 = __half22float2(__ldg(xh + s1.w * 32 + lane));
        ax += ((v0.x + v1.x) + (v2.x + v3.x)) + ((v4.x + v5.x) + (v6.x + v7.x));
        ay += ((v0.y + v1.y) + (v2.y + v3.y)) + ((v4.y + v5.y) + (v6.y + v7.y));
    }
    for (; e + 4 <= deg; e += 4) {
        int4 s = *(const int4*)(bkt + e);
        float2 v0 = __half22float2(__ldg(xh + s.x * 32 + lane));
        float2 v1 = __half22float2(__ldg(xh + s.y * 32 + lane));
        float2 v2 = __half22float2(__ldg(xh + s.z * 32 + lane));
        float2 v3 = __half22float2(__ldg(xh + s.w * 32 + lane));
        ax += (v0.x + v1.x) + (v2.x + v3.x);
        ay += (v0.y + v1.y) + (v2.y + v3.y);
    }
    for (; e < deg; e++) {
        int s = __ldg(bkt + e);
        float2 v = __half22float2(__ldg(xh + s * 32 + lane));
        ax += v.x; ay += v.y;
    }
    float inv = 1.f / fmaxf((float)degRaw, 1.f);
    __half2 m = __floats2half2_rn(ax * inv, ay * inv);
    ((__half2*)g_meanh)[n * 32 + lane] = m;
}

// ---------------------------------------------------------------------------
// GEMM: dense A staging (x fp32-split + mean fp16->bf16 split, exact),
// split-bf16 HMMA, bias+ReLU. Block = 8 warps, 128-node tile.
// C = Ah*Bh + Ah*Bl + Al*Bh.
// ---------------------------------------------------------------------------
__global__ void __launch_bounds__(256, 2)
k_gemm(const float* __restrict__ x,
       const float* __restrict__ Ws,
       const float* __restrict__ bs,
       const float* __restrict__ Wn,
       float* __restrict__ out) {
    extern __shared__ char smem_raw[];
    uint32_t sb32 = (s2u(smem_raw) + 255u) & ~255u;
    char* smem = smem_raw + (sb32 - s2u(smem_raw));
    int tid = threadIdx.x, lane = tid & 31, wid = tid >> 5;

    // ---- stage B (weights, split) + bias ----
    for (int idx = tid; idx < 64 * 64; idx += 256) {
        int n = idx >> 6, k2 = idx & 63;
        int k0 = 2 * k2, k1 = 2 * k2 + 1;
        float w0 = (k0 < 64) ? __ldg(Ws + n * 64 + k0) : __ldg(Wn + n * 64 + (k0 - 64));
        float w1 = (k1 < 64) ? __ldg(Ws + n * 64 + k1) : __ldg(Wn + n * 64 + (k1 - 64));
        uint32_t h, l;
        bsplit(make_float2(w0, w1), h, l);
        uint32_t c = (uint32_t)(4 * k2) ^ (uint32_t)((n & 7) << 4);
        *(uint32_t*)(smem + OFF_BH + n * 256 + c) = h;
        *(uint32_t*)(smem + OFF_BL + n * 256 + c) = l;
    }
    if (tid < 64) *(float*)(smem + OFF_BIAS + tid * 4) = __ldg(bs + tid);

    // ---- stage A: coalesced x row (fp32) + mean row (fp16), split-bf16 ----
    int base = blockIdx.x * TILE_M;
    const float2* xp = (const float2*)x;
    const __half2* mp = (const __half2*)g_meanh;
    #pragma unroll 4
    for (int i = 0; i < 16; i++) {
        int r = wid * 16 + i;
        int n = base + r;
        float2 xpair = make_float2(0.f, 0.f), mpair = make_float2(0.f, 0.f);
        if (n < NN) {
            xpair = __ldg(xp + n * 32 + lane);
            mpair = __half22float2(__ldg(mp + n * 32 + lane));
        }
        uint32_t sw = (uint32_t)((r & 7) << 4);
        uint32_t hx, lx, hm, lm;
        bsplit(xpair, hx, lx);
        bsplit(mpair, hm, lm);            // exact: fp16 mantissa fits in bf16 hi+lo
        uint32_t cx = (uint32_t)(4 * lane) ^ sw;
        uint32_t cm = (uint32_t)(128 + 4 * lane) ^ sw;
        *(uint32_t*)(smem + OFF_AH + r * 256 + cx) = hx;
        *(uint32_t*)(smem + OFF_AL + r * 256 + cx) = lx;
        *(uint32_t*)(smem + OFF_AH + r * 256 + cm) = hm;
        *(uint32_t*)(smem + OFF_AL + r * 256 + cm) = lm;
    }
    __syncthreads();

    // ---- GEMM: warp w -> rows [16w,16w+16) x 64 cols ----
    int rm = wid * 16;
    int arow = rm + (lane & 7) + ((lane >> 3) & 1) * 8;
    uint32_t koffA = (uint32_t)((lane >> 4) * 16);
    uint32_t swA = (uint32_t)((arow & 7) << 4);
    uint32_t aBase = sb32 + OFF_AH + (uint32_t)arow * 256;

    int bn = (lane & 7) + ((lane >> 4) << 3);
    uint32_t koffB = (uint32_t)(((lane >> 3) & 1) * 16);
    uint32_t swB = (uint32_t)((bn & 7) << 4);
    uint32_t bBase = sb32 + OFF_BH + (uint32_t)bn * 256;

    float c[8][4];
    #pragma unroll
    for (int nt = 0; nt < 8; nt++)
        c[nt][0] = c[nt][1] = c[nt][2] = c[nt][3] = 0.f;

    #pragma unroll
    for (int ks = 0; ks < 8; ks++) {
        uint32_t ah[4], al[4];
        uint32_t aaddr = aBase + (((uint32_t)(ks * 32) + koffA) ^ swA);
        ldsm4(ah, aaddr);
        ldsm4(al, aaddr + 32768);
        uint32_t kbA = ((uint32_t)(ks * 32) + koffB) ^ swB;
        #pragma unroll
        for (int np = 0; np < 4; np++) {
            uint32_t bh[4], bl[4];
            uint32_t baddr = bBase + (uint32_t)(np * 4096) + kbA;
            ldsm4(bh, baddr);
            ldsm4(bl, baddr + 16384);
            mma16816(c[2 * np],     ah, bh);
            mma16816(c[2 * np],     ah, bl);
            mma16816(c[2 * np],     al, bh);
            mma16816(c[2 * np + 1], ah, bh + 2);
            mma16816(c[2 * np + 1], ah, bl + 2);
            mma16816(c[2 * np + 1], al, bh + 2);
        }
    }

    // ---- epilogue: bias + relu + store ----
    const float* bias = (const float*)(smem + OFF_BIAS);
    int r0 = base + rm + (lane >> 2);
    int colq = (lane & 3) * 2;
    #pragma unroll
    for (int nt = 0; nt < 8; nt++) {
        int col = nt * 8 + colq;
        float b0 = bias[col], b1 = bias[col + 1];
        if (r0 < NN) {
            float2 v;
            v.x = fmaxf(c[nt][0] + b0, 0.f);
            v.y = fmaxf(c[nt][1] + b1, 0.f);
            *(float2*)(out + (size_t)r0 * 64 + col) = v;
        }
        if (r0 + 8 < NN) {
            float2 v;
            v.x = fmaxf(c[nt][2] + b0, 0.f);
            v.y = fmaxf(c[nt][3] + b1, 0.f);
            *(float2*)(out + (size_t)(r0 + 8) * 64 + col) = v;
        }
    }
}

// ---------------------------------------------------------------------------
extern "C" void kernel_launch(void* const* d_in, const int* in_sizes, int n_in,
                              void* d_out, int out_size) {
    const float* x  = (const float*)d_in[0];
    const int*   ei = (const int*)  d_in[1];
    const float* Ws = (const float*)d_in[2];
    const float* bs = (const float*)d_in[3];
    const float* Wn = (const float*)d_in[4];
    float* out = (float*)d_out;
    int E = in_sizes[1] / 2;

    cudaFuncSetAttribute(k_gemm, cudaFuncAttributeMaxDynamicSharedMemorySize, SMEM_DYN);

    void* cnt_ptr = nullptr;
    cudaGetSymbolAddress(&cnt_ptr, g_cnt);
    cudaMemsetAsync(cnt_ptr, 0, NN * sizeof(int));

    k_convert<<<(NN * 16 + 255) / 256, 256>>>(x);
    k_scatter<<<((E + 1) / 2 + 255) / 256, 256>>>(ei, E);
    k_gather<<<(NN + 7) / 8, 256>>>();
    k_gemm<<<NTILES, 256, SMEM_DYN>>>(x, Ws, bs, Wn, out);
}

// round 11
// speedup vs baseline: 1.2393x; 1.2393x over previous
#include <cuda_runtime.h>
#include <cuda_fp16.h>
#include <stdint.h>

#define NN 100000
#define NE 1250000
#define BKT 64
#define TILE_M 128
#define NTILES ((NN + TILE_M - 1) / TILE_M)   // 782

// ---- static device scratch (no allocations) ----
__device__ int    g_cnt[NN];           // degree counter / scatter cursor
__device__ int    g_src[NN * BKT];     // padded neighbor buckets (25.6 MB)
__device__ __half g_xh[NN * 64];       // fp16 copy of x (12.8 MB)
__device__ __half g_meanh[NN * 64];    // neighbor means, fp16 (12.8 MB)
__device__ __half g_wh[64 * 128];      // W' = [Ws | Wn] per out-row, fp16 (16 KB)

// ---- k_gemm shared layout (byte offsets; rows 256B, XOR-16B swizzled) ----
#define OFF_A    0        // A: 128 rows x 128 fp16 (x||mean) = 256B/row, 32 KB
#define OFF_B    32768    // B: 64 rows x 128 fp16 = 256B/row, 16 KB
#define OFF_BIAS 49152    // 64 floats
#define SMEM_USE 49408
#define SMEM_DYN (SMEM_USE + 256)

__device__ __forceinline__ uint32_t s2u(const void* p) {
    uint32_t a;
    asm("{ .reg .u64 t; cvta.to.shared.u64 t, %1; cvt.u32.u64 %0, t; }" : "=r"(a) : "l"(p));
    return a;
}
__device__ __forceinline__ void ldsm4(uint32_t* r, uint32_t addr) {
    asm volatile("ldmatrix.sync.aligned.m8n8.x4.shared.b16 {%0,%1,%2,%3}, [%4];"
                 : "=r"(r[0]), "=r"(r[1]), "=r"(r[2]), "=r"(r[3]) : "r"(addr));
}
__device__ __forceinline__ void mma16816h(float* c, const uint32_t* a, const uint32_t* b) {
    asm volatile(
        "mma.sync.aligned.m16n8k16.row.col.f32.f16.f16.f32 "
        "{%0,%1,%2,%3}, {%4,%5,%6,%7}, {%8,%9}, {%0,%1,%2,%3};"
        : "+f"(c[0]), "+f"(c[1]), "+f"(c[2]), "+f"(c[3])
        : "r"(a[0]), "r"(a[1]), "r"(a[2]), "r"(a[3]), "r"(b[0]), "r"(b[1]));
}

// ---------------------------------------------------------------------------
// Prep (heterogeneous): blocks [0,SB) scatter edges into buckets;
// [SB, SB+CB) convert x -> fp16; last block converts W' -> fp16.
// ---------------------------------------------------------------------------
#define SCAT_B (((NE + 1) / 2 + 255) / 256)       // 2442
#define CONV_B ((NN * 16 + 255) / 256)            // 6250

__global__ void k_prep(const float* __restrict__ x,
                       const int* __restrict__ ei,
                       const float* __restrict__ Ws,
                       const float* __restrict__ Wn,
                       int E) {
    int b = blockIdx.x, tid = threadIdx.x;
    if (b < SCAT_B) {
        int e = (b * 256 + tid) * 2;
        if (e + 1 < E) {
            int2 s = *(const int2*)(ei + e);
            int2 d = *(const int2*)(ei + E + e);
            int p0 = atomicAdd(&g_cnt[d.x], 1);
            if (p0 < BKT) g_src[d.x * BKT + p0] = s.x;
            int p1 = atomicAdd(&g_cnt[d.y], 1);
            if (p1 < BKT) g_src[d.y * BKT + p1] = s.y;
        } else if (e < E) {
            int src = __ldg(ei + e);
            int dst = __ldg(ei + E + e);
            int p = atomicAdd(&g_cnt[dst], 1);
            if (p < BKT) g_src[dst * BKT + p] = src;
        }
    } else if (b < SCAT_B + CONV_B) {
        int i = (b - SCAT_B) * 256 + tid;          // float4 index
        if (i < NN * 16) {
            float4 v = __ldg((const float4*)x + i);
            __half2 h0 = __floats2half2_rn(v.x, v.y);
            __half2 h1 = __floats2half2_rn(v.z, v.w);
            uint2 o;
            o.x = *(uint32_t*)&h0;
            o.y = *(uint32_t*)&h1;
            ((uint2*)g_xh)[i] = o;
        }
    } else {
        // W': 64 rows x 128 k, row n = [Ws[n][0..63] | Wn[n][0..63]]
        for (int idx = tid; idx < 64 * 128; idx += 256) {
            int n = idx >> 7, k = idx & 127;
            float w = (k < 64) ? __ldg(Ws + n * 64 + k) : __ldg(Wn + n * 64 + (k - 64));
            g_wh[idx] = __float2half_rn(w);
        }
    }
}

// ---------------------------------------------------------------------------
// Gather: warp per node; fp16 neighbor rows, fp32 accum, fp16 mean out.
// Tail handled with masked 4-wide chunks (indices clamped, weights zeroed).
// ---------------------------------------------------------------------------
__global__ void __launch_bounds__(256)
k_gather() {
    int n = (blockIdx.x * 256 + threadIdx.x) >> 5;
    int lane = threadIdx.x & 31;
    if (n >= NN) return;
    const __half2* xh = (const __half2*)g_xh;

    int degRaw = __ldg(&g_cnt[n]);
    int deg = min(degRaw, BKT);
    const int* bkt = g_src + n * BKT;
    float ax = 0.f, ay = 0.f;
    int e = 0;
    for (; e + 8 <= deg; e += 8) {                  // MLP = 8
        int4 s0 = *(const int4*)(bkt + e);
        int4 s1 = *(const int4*)(bkt + e + 4);
        float2 v0 = __half22float2(__ldg(xh + s0.x * 32 + lane));
        float2 v1 = __half22float2(__ldg(xh + s0.y * 32 + lane));
        float2 v2 = __half22float2(__ldg(xh + s0.z * 32 + lane));
        float2 v3 = __half22float2(__ldg(xh + s0.w * 32 + lane));
        float2 v4 = __half22float2(__ldg(xh + s1.x * 32 + lane));
        float2 v5 = __half22float2(__ldg(xh + s1.y * 32 + lane));
        float2 v6 = __half22float2(__ldg(xh + s1.z * 32 + lane));
        float2 v7 = __half22float2(__ldg(xh + s1.w * 32 + lane));
        ax += ((v0.x + v1.x) + (v2.x + v3.x)) + ((v4.x + v5.x) + (v6.x + v7.x));
        ay += ((v0.y + v1.y) + (v2.y + v3.y)) + ((v4.y + v5.y) + (v6.y + v7.y));
    }
    for (; e < deg; e += 4) {                       // masked tail, MLP = 4
        int4 s = *(const int4*)(bkt + e);
        int   i0 = s.x;
        float w1 = (e + 1 < deg) ? 1.f : 0.f;
        float w2 = (e + 2 < deg) ? 1.f : 0.f;
        float w3 = (e + 3 < deg) ? 1.f : 0.f;
        int   i1 = (e + 1 < deg) ? s.y : 0;
        int   i2 = (e + 2 < deg) ? s.z : 0;
        int   i3 = (e + 3 < deg) ? s.w : 0;
        float2 v0 = __half22float2(__ldg(xh + i0 * 32 + lane));
        float2 v1 = __half22float2(__ldg(xh + i1 * 32 + lane));
        float2 v2 = __half22float2(__ldg(xh + i2 * 32 + lane));
        float2 v3 = __half22float2(__ldg(xh + i3 * 32 + lane));
        ax += v0.x + w1 * v1.x + w2 * v2.x + w3 * v3.x;
        ay += v0.y + w1 * v1.y + w2 * v2.y + w3 * v3.y;
    }
    float inv = 1.f / fmaxf((float)degRaw, 1.f);
    __half2 m = __floats2half2_rn(ax * inv, ay * inv);
    ((__half2*)g_meanh)[n * 32 + lane] = m;
}

// ---------------------------------------------------------------------------
// GEMM: single-pass fp16 HMMA. A rows copied straight from g_xh/g_meanh,
// B from g_wh. Block = 8 warps, 128-node tile. 48.5KB smem -> 4 CTA/SM.
// ---------------------------------------------------------------------------
__global__ void __launch_bounds__(256, 4)
k_gemm(const float* __restrict__ bs,
       float* __restrict__ out) {
    extern __shared__ char smem_raw[];
    uint32_t sb32 = (s2u(smem_raw) + 255u) & ~255u;
    char* smem = smem_raw + (sb32 - s2u(smem_raw));
    int tid = threadIdx.x, lane = tid & 31, wid = tid >> 5;

    // ---- stage B: 16KB fp16 copy, 256B rows, swizzled (FIXED: full row) ----
    for (int idx = tid; idx < 64 * 64; idx += 256) {        // uint32 elements
        int n = idx >> 6, k2 = idx & 63;                     // 64 uint32 = 256B per row
        uint32_t v = ((const uint32_t*)g_wh)[idx];
        uint32_t c = (uint32_t)(4 * k2) ^ (uint32_t)((n & 7) << 4);
        *(uint32_t*)(smem + OFF_B + n * 256 + c) = v;
    }
    if (tid < 64) *(float*)(smem + OFF_BIAS + tid * 4) = __ldg(bs + tid);

    // ---- stage A: direct fp16 row copies (x || mean), swizzled ----
    int base = blockIdx.x * TILE_M;
    const uint32_t* xp = (const uint32_t*)g_xh;
    const uint32_t* mp = (const uint32_t*)g_meanh;
    #pragma unroll 4
    for (int i = 0; i < 16; i++) {
        int r = wid * 16 + i;
        int n = base + r;
        uint32_t xv = 0, mv = 0;
        if (n < NN) {
            xv = __ldg(xp + n * 32 + lane);
            mv = __ldg(mp + n * 32 + lane);
        }
        uint32_t sw = (uint32_t)((r & 7) << 4);
        uint32_t cx = (uint32_t)(4 * lane) ^ sw;
        uint32_t cm = (uint32_t)(128 + 4 * lane) ^ sw;
        *(uint32_t*)(smem + OFF_A + r * 256 + cx) = xv;
        *(uint32_t*)(smem + OFF_A + r * 256 + cm) = mv;
    }
    __syncthreads();

    // ---- GEMM: warp w -> rows [16w,16w+16) x 64 cols ----
    int rm = wid * 16;
    int arow = rm + (lane & 7) + ((lane >> 3) & 1) * 8;
    uint32_t koffA = (uint32_t)((lane >> 4) * 16);
    uint32_t swA = (uint32_t)((arow & 7) << 4);
    uint32_t aBase = sb32 + OFF_A + (uint32_t)arow * 256;

    // B rows are 256B (FIXED); np tile = 16 rows = 4096B
    int bn = (lane & 7) + ((lane >> 4) << 3);
    uint32_t koffB = (uint32_t)(((lane >> 3) & 1) * 16);
    uint32_t swB = (uint32_t)((bn & 7) << 4);
    uint32_t bBase = sb32 + OFF_B + (uint32_t)bn * 256;

    float c[8][4];
    #pragma unroll
    for (int nt = 0; nt < 8; nt++)
        c[nt][0] = c[nt][1] = c[nt][2] = c[nt][3] = 0.f;

    #pragma unroll
    for (int ks = 0; ks < 8; ks++) {
        uint32_t a[4];
        ldsm4(a, aBase + (((uint32_t)(ks * 32) + koffA) ^ swA));
        uint32_t kbB = ((uint32_t)(ks * 32) + koffB) ^ swB;
        #pragma unroll
        for (int np = 0; np < 4; np++) {
            uint32_t bfr[4];
            ldsm4(bfr, bBase + (uint32_t)(np * 4096) + kbB);
            mma16816h(c[2 * np],     a, bfr);
            mma16816h(c[2 * np + 1], a, bfr + 2);
        }
    }

    // ---- epilogue: bias + relu + store ----
    const float* bias = (const float*)(smem + OFF_BIAS);
    int r0 = base + rm + (lane >> 2);
    int colq = (lane & 3) * 2;
    #pragma unroll
    for (int nt = 0; nt < 8; nt++) {
        int col = nt * 8 + colq;
        float b0 = bias[col], b1 = bias[col + 1];
        if (r0 < NN) {
            float2 v;
            v.x = fmaxf(c[nt][0] + b0, 0.f);
            v.y = fmaxf(c[nt][1] + b1, 0.f);
            *(float2*)(out + (size_t)r0 * 64 + col) = v;
        }
        if (r0 + 8 < NN) {
            float2 v;
            v.x = fmaxf(c[nt][2] + b0, 0.f);
            v.y = fmaxf(c[nt][3] + b1, 0.f);
            *(float2*)(out + (size_t)(r0 + 8) * 64 + col) = v;
        }
    }
}

// ---------------------------------------------------------------------------
extern "C" void kernel_launch(void* const* d_in, const int* in_sizes, int n_in,
                              void* d_out, int out_size) {
    const float* x  = (const float*)d_in[0];
    const int*   ei = (const int*)  d_in[1];
    const float* Ws = (const float*)d_in[2];
    const float* bs = (const float*)d_in[3];
    const float* Wn = (const float*)d_in[4];
    float* out = (float*)d_out;
    int E = in_sizes[1] / 2;

    cudaFuncSetAttribute(k_gemm, cudaFuncAttributeMaxDynamicSharedMemorySize, SMEM_DYN);

    void* cnt_ptr = nullptr;
    cudaGetSymbolAddress(&cnt_ptr, g_cnt);
    cudaMemsetAsync(cnt_ptr, 0, NN * sizeof(int));

    k_prep<<<SCAT_B + CONV_B + 1, 256>>>(x, ei, Ws, Wn, E);
    k_gather<<<(NN + 7) / 8, 256>>>();
    k_gemm<<<NTILES, 256, SMEM_DYN>>>(bs, out);
}